// round 7
// baseline (speedup 1.0000x reference)
#include <cuda_runtime.h>

// Problem constants (fixed by setup_inputs)
namespace {
constexpr int BTOT = 32768;
constexpr int T = 28;
constexpr int D = 28;
constexpr int H = 10;
constexpr int G = 40;      // 4*H
constexpr int HP = 12;     // H padded to multiple of 4 for float4 LDS
constexpr int BLK = 64;    // threads per CTA
constexpr int SPT = 2;     // samples per thread
constexpr int ROWS = BLK * SPT;   // 128 samples per CTA
constexpr int SXS = 29;    // padded x-tile row stride (conflict-free scalar LDS)

__device__ __forceinline__ float sigm(float x) {
    float e = __expf(-x);                       // MUFU.EX2
    return __fdividef(1.0f, 1.0f + e);          // MUFU.RCP
}
__device__ __forceinline__ float tanh_(float x) {
    float e = __expf(2.0f * x);
    return 1.0f - __fdividef(2.0f, e + 1.0f);
}

__global__ void __launch_bounds__(BLK) lstm_fused(
    const float* __restrict__ x,
    const float* __restrict__ w_ih0, const float* __restrict__ w_hh0,
    const float* __restrict__ b_ih0, const float* __restrict__ b_hh0,
    const float* __restrict__ w_ih1, const float* __restrict__ w_hh1,
    const float* __restrict__ b_ih1, const float* __restrict__ b_hh1,
    const float* __restrict__ w_cls, const float* __restrict__ b_cls,
    float* __restrict__ out)
{
    __shared__ __align__(16) float s_w0i[G * D];    // [40][28] rows 112B (16B-mult)
    __shared__ __align__(16) float s_w0h[G * HP];   // [40][12] zero-padded
    __shared__ __align__(16) float s_w1i[G * HP];
    __shared__ __align__(16) float s_w1h[G * HP];
    __shared__ __align__(16) float s_wc[10 * HP];
    __shared__ float s_b0[G];
    __shared__ float s_b1[G];
    __shared__ float s_bc[16];
    __shared__ float s_x[ROWS * SXS];               // 128 sample rows, stride 29

    const int tid = threadIdx.x;

    // ---- stage weights into smem (once) ----
    for (int i = tid; i < G * D; i += BLK) s_w0i[i] = w_ih0[i];
    for (int i = tid; i < G * HP; i += BLK) {
        int r = i / HP, c2 = i - r * HP;
        bool v = (c2 < H);
        s_w0h[i] = v ? w_hh0[r * H + c2] : 0.0f;
        s_w1i[i] = v ? w_ih1[r * H + c2] : 0.0f;
        s_w1h[i] = v ? w_hh1[r * H + c2] : 0.0f;
    }
    for (int i = tid; i < 10 * HP; i += BLK) {
        int r = i / HP, c2 = i - r * HP;
        s_wc[i] = (c2 < H) ? w_cls[r * H + c2] : 0.0f;
    }
    for (int i = tid; i < G; i += BLK) {
        s_b0[i] = b_ih0[i] + b_hh0[i];
        s_b1[i] = b_ih1[i] + b_hh1[i];
    }
    if (tid < 10) s_bc[tid] = b_cls[tid];
    __syncthreads();

    const float* xblk = x + (size_t)blockIdx.x * ROWS * (T * D);

    // per-(thread,sample) state; pads kept zero so float4 recurrent FMAs are safe
    float h0[SPT][HP], h1[SPT][HP], hn[SPT][HP], hn1[SPT][H], c0[SPT][H], c1[SPT][H];
    #pragma unroll
    for (int j = 0; j < SPT; j++) {
        #pragma unroll
        for (int i = 0; i < HP; i++) { h0[j][i] = 0.0f; h1[j][i] = 0.0f; hn[j][i] = 0.0f; }
        #pragma unroll
        for (int i = 0; i < H; i++) { c0[j][i] = 0.0f; c1[j][i] = 0.0f; }
    }

    // staging index decomposition: e = k*BLK + tid ; s = e/D ; d = e%D
    const int s_init = tid / D;
    const int d_init = tid - s_init * D;

    for (int t = 0; t < T; t++) {
        __syncthreads();   // previous tile fully consumed
        {
            // cooperative coalesced load of x[128 rows][t][0..27]
            const float* src = xblk + t * D;
            int e = tid, s = s_init, d = d_init;
            #pragma unroll
            for (int k = 0; k < ROWS * D / BLK; k++) {   // 56 iterations
                s_x[e + s] = src[e + s * (T * D - D)];   // smem: s*29+d ; gmem: s*784+d
                e += BLK;
                d += (BLK - 2 * D);  // +8
                s += 2;
                if (d >= D) { d -= D; s += 1; }
            }
        }
        __syncthreads();

        float xr[SPT][D];
        #pragma unroll
        for (int j = 0; j < SPT; j++)
            #pragma unroll
            for (int dd = 0; dd < D; dd++)
                xr[j][dd] = s_x[(tid + j * BLK) * SXS + dd];

        // ---------- layer 0 ----------
        #pragma unroll
        for (int u = 0; u < H; u++) {
            float gi[SPT], gf[SPT], gg[SPT], go[SPT];
            #pragma unroll
            for (int j = 0; j < SPT; j++) {
                gi[j] = s_b0[u]; gf[j] = s_b0[u + H];
                gg[j] = s_b0[u + 2 * H]; go[j] = s_b0[u + 3 * H];
            }
            const float4* wi = (const float4*)(s_w0i + u * D);
            const float4* wf = (const float4*)(s_w0i + (u + H) * D);
            const float4* wg = (const float4*)(s_w0i + (u + 2 * H) * D);
            const float4* wo = (const float4*)(s_w0i + (u + 3 * H) * D);
            #pragma unroll
            for (int q = 0; q < D / 4; q++) {
                float4 a = wi[q], b = wf[q], c = wg[q], dd = wo[q];
                #pragma unroll
                for (int j = 0; j < SPT; j++) {
                    gi[j] += a.x * xr[j][4*q];   gi[j] += a.y * xr[j][4*q+1];
                    gi[j] += a.z * xr[j][4*q+2]; gi[j] += a.w * xr[j][4*q+3];
                    gf[j] += b.x * xr[j][4*q];   gf[j] += b.y * xr[j][4*q+1];
                    gf[j] += b.z * xr[j][4*q+2]; gf[j] += b.w * xr[j][4*q+3];
                    gg[j] += c.x * xr[j][4*q];   gg[j] += c.y * xr[j][4*q+1];
                    gg[j] += c.z * xr[j][4*q+2]; gg[j] += c.w * xr[j][4*q+3];
                    go[j] += dd.x * xr[j][4*q];   go[j] += dd.y * xr[j][4*q+1];
                    go[j] += dd.z * xr[j][4*q+2]; go[j] += dd.w * xr[j][4*q+3];
                }
            }
            const float4* ri = (const float4*)(s_w0h + u * HP);
            const float4* rf = (const float4*)(s_w0h + (u + H) * HP);
            const float4* rg = (const float4*)(s_w0h + (u + 2 * H) * HP);
            const float4* ro = (const float4*)(s_w0h + (u + 3 * H) * HP);
            #pragma unroll
            for (int q = 0; q < HP / 4; q++) {
                float4 a = ri[q], b = rf[q], c = rg[q], dd = ro[q];
                #pragma unroll
                for (int j = 0; j < SPT; j++) {
                    gi[j] += a.x * h0[j][4*q];   gi[j] += a.y * h0[j][4*q+1];
                    gi[j] += a.z * h0[j][4*q+2]; gi[j] += a.w * h0[j][4*q+3];
                    gf[j] += b.x * h0[j][4*q];   gf[j] += b.y * h0[j][4*q+1];
                    gf[j] += b.z * h0[j][4*q+2]; gf[j] += b.w * h0[j][4*q+3];
                    gg[j] += c.x * h0[j][4*q];   gg[j] += c.y * h0[j][4*q+1];
                    gg[j] += c.z * h0[j][4*q+2]; gg[j] += c.w * h0[j][4*q+3];
                    go[j] += dd.x * h0[j][4*q];   go[j] += dd.y * h0[j][4*q+1];
                    go[j] += dd.z * h0[j][4*q+2]; go[j] += dd.w * h0[j][4*q+3];
                }
            }
            #pragma unroll
            for (int j = 0; j < SPT; j++) {
                float ig = sigm(gi[j]), fg = sigm(gf[j]);
                float gt = tanh_(gg[j]), og = sigm(go[j]);
                float cn = fg * c0[j][u] + ig * gt;
                c0[j][u] = cn;
                hn[j][u] = og * tanh_(cn);
            }
        }

        // ---------- layer 1 (input = hn, recurrent = h1) ----------
        #pragma unroll
        for (int u = 0; u < H; u++) {
            float gi[SPT], gf[SPT], gg[SPT], go[SPT];
            #pragma unroll
            for (int j = 0; j < SPT; j++) {
                gi[j] = s_b1[u]; gf[j] = s_b1[u + H];
                gg[j] = s_b1[u + 2 * H]; go[j] = s_b1[u + 3 * H];
            }
            const float4* wi = (const float4*)(s_w1i + u * HP);
            const float4* wf = (const float4*)(s_w1i + (u + H) * HP);
            const float4* wg = (const float4*)(s_w1i + (u + 2 * H) * HP);
            const float4* wo = (const float4*)(s_w1i + (u + 3 * H) * HP);
            #pragma unroll
            for (int q = 0; q < HP / 4; q++) {
                float4 a = wi[q], b = wf[q], c = wg[q], dd = wo[q];
                #pragma unroll
                for (int j = 0; j < SPT; j++) {
                    gi[j] += a.x * hn[j][4*q];   gi[j] += a.y * hn[j][4*q+1];
                    gi[j] += a.z * hn[j][4*q+2]; gi[j] += a.w * hn[j][4*q+3];
                    gf[j] += b.x * hn[j][4*q];   gf[j] += b.y * hn[j][4*q+1];
                    gf[j] += b.z * hn[j][4*q+2]; gf[j] += b.w * hn[j][4*q+3];
                    gg[j] += c.x * hn[j][4*q];   gg[j] += c.y * hn[j][4*q+1];
                    gg[j] += c.z * hn[j][4*q+2]; gg[j] += c.w * hn[j][4*q+3];
                    go[j] += dd.x * hn[j][4*q];   go[j] += dd.y * hn[j][4*q+1];
                    go[j] += dd.z * hn[j][4*q+2]; go[j] += dd.w * hn[j][4*q+3];
                }
            }
            const float4* ri = (const float4*)(s_w1h + u * HP);
            const float4* rf = (const float4*)(s_w1h + (u + H) * HP);
            const float4* rg = (const float4*)(s_w1h + (u + 2 * H) * HP);
            const float4* ro = (const float4*)(s_w1h + (u + 3 * H) * HP);
            #pragma unroll
            for (int q = 0; q < HP / 4; q++) {
                float4 a = ri[q], b = rf[q], c = rg[q], dd = ro[q];
                #pragma unroll
                for (int j = 0; j < SPT; j++) {
                    gi[j] += a.x * h1[j][4*q];   gi[j] += a.y * h1[j][4*q+1];
                    gi[j] += a.z * h1[j][4*q+2]; gi[j] += a.w * h1[j][4*q+3];
                    gf[j] += b.x * h1[j][4*q];   gf[j] += b.y * h1[j][4*q+1];
                    gf[j] += b.z * h1[j][4*q+2]; gf[j] += b.w * h1[j][4*q+3];
                    gg[j] += c.x * h1[j][4*q];   gg[j] += c.y * h1[j][4*q+1];
                    gg[j] += c.z * h1[j][4*q+2]; gg[j] += c.w * h1[j][4*q+3];
                    go[j] += dd.x * h1[j][4*q];   go[j] += dd.y * h1[j][4*q+1];
                    go[j] += dd.z * h1[j][4*q+2]; go[j] += dd.w * h1[j][4*q+3];
                }
            }
            #pragma unroll
            for (int j = 0; j < SPT; j++) {
                float ig = sigm(gi[j]), fg = sigm(gf[j]);
                float gt = tanh_(gg[j]), og = sigm(go[j]);
                float cn = fg * c1[j][u] + ig * gt;
                c1[j][u] = cn;
                hn1[j][u] = og * tanh_(cn);
            }
        }

        #pragma unroll
        for (int j = 0; j < SPT; j++)
            #pragma unroll
            for (int u = 0; u < H; u++) { h0[j][u] = hn[j][u]; h1[j][u] = hn1[j][u]; }
    }

    // ---------- classifier: out[b] = h1 @ w_cls^T + b_cls ----------
    #pragma unroll
    for (int j = 0; j < SPT; j++) {
        const size_t b = (size_t)blockIdx.x * ROWS + tid + j * BLK;
        #pragma unroll
        for (int k = 0; k < 10; k++) {
            const float4* w = (const float4*)(s_wc + k * HP);
            float acc = s_bc[k];
            #pragma unroll
            for (int q = 0; q < HP / 4; q++) {
                float4 a = w[q];
                acc += a.x * h1[j][4*q];   acc += a.y * h1[j][4*q+1];
                acc += a.z * h1[j][4*q+2]; acc += a.w * h1[j][4*q+3];
            }
            out[b * 10 + k] = acc;
        }
    }
}
} // namespace

extern "C" void kernel_launch(void* const* d_in, const int* in_sizes, int n_in,
                              void* d_out, int out_size)
{
    (void)in_sizes; (void)n_in; (void)out_size;
    const float* x     = (const float*)d_in[0];
    const float* w_ih0 = (const float*)d_in[1];
    const float* w_hh0 = (const float*)d_in[2];
    const float* b_ih0 = (const float*)d_in[3];
    const float* b_hh0 = (const float*)d_in[4];
    const float* w_ih1 = (const float*)d_in[5];
    const float* w_hh1 = (const float*)d_in[6];
    const float* b_ih1 = (const float*)d_in[7];
    const float* b_hh1 = (const float*)d_in[8];
    const float* w_cls = (const float*)d_in[9];
    const float* b_cls = (const float*)d_in[10];

    lstm_fused<<<BTOT / (BLK * SPT), BLK>>>(x, w_ih0, w_hh0, b_ih0, b_hh0,
                                            w_ih1, w_hh1, b_ih1, b_hh1,
                                            w_cls, b_cls, (float*)d_out);
}

// round 9
// speedup vs baseline: 1.5325x; 1.5325x over previous
#include <cuda_runtime.h>
#include <cstdint>

namespace {
constexpr int BTOT = 32768;
constexpr int T = 28;
constexpr int D = 28;
constexpr int H = 10;
constexpr int G = 40;      // 4*H
constexpr int HP = 12;     // H padded (zero) for packed recurrent matvec
constexpr int BLK = 128;   // recurrent kernel: threads (=samples) per CTA
constexpr int SGX = 44;    // padded s_xg row stride in floats (16B-mult, conflict-ok)

// 147MB scratch: xg0[s][t][g] = x . w_ih0^T + b_ih0 + b_hh0
__device__ float g_xg[(size_t)BTOT * T * G];

__device__ __forceinline__ float sigm(float x) {
    float e = __expf(-x);
    return __fdividef(1.0f, 1.0f + e);
}
__device__ __forceinline__ float tanh_(float x) {
    float e = __expf(2.0f * x);
    return 1.0f - __fdividef(2.0f, e + 1.0f);
}

// ---- packed f32x2 helpers (ptxas never auto-emits FFMA2; hand PTX) ----
__device__ __forceinline__ uint64_t dup2(float v) {
    uint64_t r;
    asm("mov.b64 %0, {%1, %1};" : "=l"(r) : "f"(v));
    return r;
}
__device__ __forceinline__ void fma2(uint64_t& d, uint64_t a, uint64_t b) {
    asm("fma.rn.f32x2 %0, %1, %2, %0;" : "+l"(d) : "l"(a), "l"(b));
}
__device__ __forceinline__ void unp2(uint64_t p, float& lo, float& hi) {
    asm("mov.b64 {%0, %1}, %2;" : "=f"(lo), "=f"(hi) : "l"(p));
}

// ============================================================
// Kernel A: xg0[row][g] = x[row] . w_ih0^T + (b_ih0 + b_hh0)
// row = s*T + t, 917504 rows, one thread per row.
// Output rows paired (2j,2j+1) -> f32x2 accumulators; weights stored
// interleaved in smem so ld.shared.v2.u64 yields ready-packed operands.
// ============================================================
__global__ void __launch_bounds__(256) xproj(
    const float* __restrict__ x,
    const float* __restrict__ w_ih0,
    const float* __restrict__ b_ih0,
    const float* __restrict__ b_hh0)
{
    __shared__ __align__(16) float s_w[20 * D * 2];  // [j][d][l] = w_ih0[(2j+l)*D + d]
    __shared__ __align__(16) float s_b[G];

    const int tid = threadIdx.x;
    for (int i = tid; i < 20 * D * 2; i += 256) {
        int l = i & 1, rest = i >> 1;
        int d = rest % D, j = rest / D;
        s_w[j * (2 * D) + d * 2 + l] = w_ih0[(2 * j + l) * D + d];
    }
    for (int i = tid; i < G; i += 256) s_b[i] = b_ih0[i] + b_hh0[i];
    __syncthreads();

    const int row = blockIdx.x * 256 + tid;   // grid sized exactly

    // load x row (28 contiguous floats, 16B aligned)
    float xv[D];
    const float4* xr = reinterpret_cast<const float4*>(x + (size_t)row * D);
    #pragma unroll
    for (int q = 0; q < D / 4; q++) {
        float4 v = xr[q];
        xv[4 * q] = v.x; xv[4 * q + 1] = v.y; xv[4 * q + 2] = v.z; xv[4 * q + 3] = v.w;
    }
    uint64_t xd[D];
    #pragma unroll
    for (int d = 0; d < D; d++) xd[d] = dup2(xv[d]);

    uint64_t acc[20];
    #pragma unroll
    for (int j = 0; j < 20; j++) acc[j] = *(const uint64_t*)(s_b + 2 * j);

    #pragma unroll
    for (int j = 0; j < 20; j++) {
        const ulonglong2* wp = (const ulonglong2*)(s_w + j * (2 * D));
        #pragma unroll
        for (int q = 0; q < D / 2; q++) {
            ulonglong2 w = wp[q];                 // {rows(2j,2j+1)@d=2q , @d=2q+1}
            fma2(acc[j], w.x, xd[2 * q]);
            fma2(acc[j], w.y, xd[2 * q + 1]);
        }
    }

    float o[G];
    #pragma unroll
    for (int j = 0; j < 20; j++) unp2(acc[j], o[2 * j], o[2 * j + 1]);

    float4* dst = reinterpret_cast<float4*>(g_xg + (size_t)row * G);
    #pragma unroll
    for (int q = 0; q < G / 4; q++)
        dst[q] = make_float4(o[4 * q], o[4 * q + 1], o[4 * q + 2], o[4 * q + 3]);
}

// ============================================================
// Kernel B: recurrent LSTM (both layers) + classifier.
// One thread per sample; all matvecs packed f32x2 over output-row pairs.
// ============================================================
__global__ void __launch_bounds__(BLK) lstm_rec(
    const float* __restrict__ w_hh0,
    const float* __restrict__ w_ih1, const float* __restrict__ w_hh1,
    const float* __restrict__ b_ih1, const float* __restrict__ b_hh1,
    const float* __restrict__ w_cls, const float* __restrict__ b_cls,
    float* __restrict__ out)
{
    // packed weights: [j][k][l] = W[(2j+l)][k], k padded to HP=12 with zeros
    __shared__ __align__(16) float s_w0h[20 * HP * 2];
    __shared__ __align__(16) float s_w1i[20 * HP * 2];
    __shared__ __align__(16) float s_w1h[20 * HP * 2];
    __shared__ __align__(16) float s_b1[G];
    __shared__ __align__(16) float s_wc[10 * HP];
    __shared__ float s_bc[16];
    __shared__ __align__(16) float s_xg[BLK * SGX];

    const int tid = threadIdx.x;

    for (int i = tid; i < 20 * HP * 2; i += BLK) {
        int l = i & 1, rest = i >> 1;
        int k = rest % HP, j = rest / HP;
        bool v = (k < H);
        s_w0h[j * (2 * HP) + k * 2 + l] = v ? w_hh0[(2 * j + l) * H + k] : 0.0f;
        s_w1i[j * (2 * HP) + k * 2 + l] = v ? w_ih1[(2 * j + l) * H + k] : 0.0f;
        s_w1h[j * (2 * HP) + k * 2 + l] = v ? w_hh1[(2 * j + l) * H + k] : 0.0f;
    }
    for (int i = tid; i < G; i += BLK) s_b1[i] = b_ih1[i] + b_hh1[i];
    for (int i = tid; i < 10 * HP; i += BLK) {
        int r = i / HP, c2 = i - r * HP;
        s_wc[i] = (c2 < H) ? w_cls[r * H + c2] : 0.0f;
    }
    if (tid < 10) s_bc[tid] = b_cls[tid];
    __syncthreads();

    const int base = blockIdx.x * BLK;   // first sample of this CTA

    float h0[HP], h1[HP], hn[HP], c0[H], c1[H];
    #pragma unroll
    for (int i = 0; i < HP; i++) { h0[i] = 0.0f; h1[i] = 0.0f; hn[i] = 0.0f; }
    #pragma unroll
    for (int i = 0; i < H; i++) { c0[i] = 0.0f; c1[i] = 0.0f; }

    for (int t = 0; t < T; t++) {
        __syncthreads();
        // stage xg rows for this CTA's 128 samples at timestep t
        #pragma unroll
        for (int k = 0; k < 10; k++) {
            int f = tid + k * BLK;          // 0..1279 float4 chunks
            int r = f / 10, q = f - 10 * r; // sample-in-CTA, chunk-in-row
            const float4 v = *(const float4*)(g_xg + ((size_t)(base + r) * T + t) * G + q * 4);
            *(float4*)(s_xg + r * SGX + q * 4) = v;
        }
        __syncthreads();

        // ---------- layer 0: acc = xg (bias folded in kernel A) + W_hh0 . h0 ----------
        uint64_t acc[20];
        {
            const ulonglong2* xgp = (const ulonglong2*)(s_xg + tid * SGX);
            #pragma unroll
            for (int q = 0; q < 10; q++) {
                ulonglong2 v = xgp[q];
                acc[2 * q] = v.x; acc[2 * q + 1] = v.y;
            }
        }
        {
            uint64_t hd[HP];
            #pragma unroll
            for (int k = 0; k < HP; k++) hd[k] = dup2(h0[k]);
            #pragma unroll
            for (int j = 0; j < 20; j++) {
                const ulonglong2* wp = (const ulonglong2*)(s_w0h + j * (2 * HP));
                #pragma unroll
                for (int q = 0; q < HP / 2; q++) {
                    ulonglong2 w = wp[q];
                    fma2(acc[j], w.x, hd[2 * q]);
                    fma2(acc[j], w.y, hd[2 * q + 1]);
                }
            }
        }
        {
            float g40[G];
            #pragma unroll
            for (int j = 0; j < 20; j++) unp2(acc[j], g40[2 * j], g40[2 * j + 1]);
            #pragma unroll
            for (int u = 0; u < H; u++) {
                float ig = sigm(g40[u]), fg = sigm(g40[u + H]);
                float gt = tanh_(g40[u + 2 * H]), og = sigm(g40[u + 3 * H]);
                float cn = fg * c0[u] + ig * gt;
                c0[u] = cn;
                hn[u] = og * tanh_(cn);
            }
        }

        // ---------- layer 1: acc = b1 + W_ih1 . hn + W_hh1 . h1 ----------
        #pragma unroll
        for (int j = 0; j < 20; j++) acc[j] = *(const uint64_t*)(s_b1 + 2 * j);
        {
            uint64_t hd[HP];
            #pragma unroll
            for (int k = 0; k < HP; k++) hd[k] = dup2(hn[k]);
            #pragma unroll
            for (int j = 0; j < 20; j++) {
                const ulonglong2* wp = (const ulonglong2*)(s_w1i + j * (2 * HP));
                #pragma unroll
                for (int q = 0; q < HP / 2; q++) {
                    ulonglong2 w = wp[q];
                    fma2(acc[j], w.x, hd[2 * q]);
                    fma2(acc[j], w.y, hd[2 * q + 1]);
                }
            }
            #pragma unroll
            for (int k = 0; k < HP; k++) hd[k] = dup2(h1[k]);
            #pragma unroll
            for (int j = 0; j < 20; j++) {
                const ulonglong2* wp = (const ulonglong2*)(s_w1h + j * (2 * HP));
                #pragma unroll
                for (int q = 0; q < HP / 2; q++) {
                    ulonglong2 w = wp[q];
                    fma2(acc[j], w.x, hd[2 * q]);
                    fma2(acc[j], w.y, hd[2 * q + 1]);
                }
            }
        }
        {
            float g40[G];
            #pragma unroll
            for (int j = 0; j < 20; j++) unp2(acc[j], g40[2 * j], g40[2 * j + 1]);
            #pragma unroll
            for (int u = 0; u < H; u++) {
                float ig = sigm(g40[u]), fg = sigm(g40[u + H]);
                float gt = tanh_(g40[u + 2 * H]), og = sigm(g40[u + 3 * H]);
                float cn = fg * c1[u] + ig * gt;
                c1[u] = cn;
                h1[u] = og * tanh_(cn);
            }
        }

        #pragma unroll
        for (int u = 0; u < H; u++) h0[u] = hn[u];
    }

    // ---------- classifier ----------
    const size_t b = (size_t)base + tid;
    #pragma unroll
    for (int k = 0; k < 10; k++) {
        const float4* w = (const float4*)(s_wc + k * HP);
        float acc = s_bc[k];
        #pragma unroll
        for (int q = 0; q < HP / 4; q++) {
            float4 a = w[q];
            acc += a.x * h1[4 * q];     acc += a.y * h1[4 * q + 1];
            acc += a.z * h1[4 * q + 2]; acc += a.w * h1[4 * q + 3];
        }
        out[b * 10 + k] = acc;
    }
}
} // namespace

extern "C" void kernel_launch(void* const* d_in, const int* in_sizes, int n_in,
                              void* d_out, int out_size)
{
    (void)in_sizes; (void)n_in; (void)out_size;
    const float* x     = (const float*)d_in[0];
    const float* w_ih0 = (const float*)d_in[1];
    const float* w_hh0 = (const float*)d_in[2];
    const float* b_ih0 = (const float*)d_in[3];
    const float* b_hh0 = (const float*)d_in[4];
    const float* w_ih1 = (const float*)d_in[5];
    const float* w_hh1 = (const float*)d_in[6];
    const float* b_ih1 = (const float*)d_in[7];
    const float* b_hh1 = (const float*)d_in[8];
    const float* w_cls = (const float*)d_in[9];
    const float* b_cls = (const float*)d_in[10];

    xproj<<<(BTOT * T) / 256, 256>>>(x, w_ih0, b_ih0, b_hh0);
    lstm_rec<<<BTOT / BLK, BLK>>>(w_hh0, w_ih1, w_hh1, b_ih1, b_hh1,
                                  w_cls, b_cls, (float*)d_out);
}

// round 10
// speedup vs baseline: 2.1518x; 1.4041x over previous
#include <cuda_runtime.h>
#include <cstdint>

namespace {
constexpr int BTOT = 32768;
constexpr int T = 28;
constexpr int D = 28;
constexpr int H = 10;
constexpr int HP = 12;     // H padded (zeros) for packed matvec
constexpr int BLK = 128;   // threads per CTA
constexpr int SPB = 64;    // samples per CTA (2 lanes per sample)
constexpr int SXS = 30;    // s_x row stride (even -> aligned LDS.64, conflict-free)

__device__ __forceinline__ float sigm(float x) {
    float e = __expf(-x);
    return __fdividef(1.0f, 1.0f + e);
}
__device__ __forceinline__ float tanh_(float x) {
    float e = __expf(2.0f * x);
    return 1.0f - __fdividef(2.0f, e + 1.0f);
}

// ---- packed f32x2 helpers (ptxas never auto-emits FFMA2) ----
__device__ __forceinline__ uint64_t dup2(float v) {
    uint64_t r;
    asm("mov.b64 %0, {%1, %1};" : "=l"(r) : "f"(v));
    return r;
}
__device__ __forceinline__ void fma2(uint64_t& d, uint64_t a, uint64_t b) {
    asm("fma.rn.f32x2 %0, %1, %2, %0;" : "+l"(d) : "l"(a), "l"(b));
}
__device__ __forceinline__ void unp2(uint64_t p, float& lo, float& hi) {
    asm("mov.b64 {%0, %1}, %2;" : "=f"(lo), "=f"(hi) : "l"(p));
}

// Packed weight layouts (smem), all zero-padded to HP in k:
//   H-mats:  s[((a*2+p)*HP + k)*2 + c] = W[(a + p*20 + c*10)*H + k]
//   x-mat :  s[((a*2+p)*D  + d)*2 + c] = W[(a + p*20 + c*10)*D + d]
// a = absolute unit 0..9; p=0 packs (i,f) rows, p=1 packs (g,o) rows;
// c selects the low/high element of the f32x2 pair.

__global__ void __launch_bounds__(BLK) lstm_all(
    const float* __restrict__ x,
    const float* __restrict__ w_ih0, const float* __restrict__ w_hh0,
    const float* __restrict__ b_ih0, const float* __restrict__ b_hh0,
    const float* __restrict__ w_ih1, const float* __restrict__ w_hh1,
    const float* __restrict__ b_ih1, const float* __restrict__ b_hh1,
    const float* __restrict__ w_cls, const float* __restrict__ b_cls,
    float* __restrict__ out)
{
    __shared__ __align__(16) float s_wx [10 * 2 * D * 2];   // 1120
    __shared__ __align__(16) float s_w0h[10 * 2 * HP * 2];  // 480
    __shared__ __align__(16) float s_w1i[10 * 2 * HP * 2];
    __shared__ __align__(16) float s_w1h[10 * 2 * HP * 2];
    __shared__ __align__(8)  float s_b0p[40];
    __shared__ __align__(8)  float s_b1p[40];
    __shared__ __align__(16) float s_wc[10 * HP];
    __shared__ float s_bc[16];
    __shared__ __align__(8)  float s_x[SPB * SXS];

    const int tid = threadIdx.x;

    // ---- stage packed weights (once) ----
    for (int i = tid; i < 10 * 2 * D * 2; i += BLK) {
        int c = i & 1, d = (i >> 1) % D, rest = (i >> 1) / D;
        int p = rest & 1, a = rest >> 1;
        s_wx[i] = w_ih0[(a + p * 20 + c * 10) * D + d];
    }
    for (int i = tid; i < 10 * 2 * HP * 2; i += BLK) {
        int c = i & 1, k = (i >> 1) % HP, rest = (i >> 1) / HP;
        int p = rest & 1, a = rest >> 1;
        int row = a + p * 20 + c * 10;
        bool v = (k < H);
        s_w0h[i] = v ? w_hh0[row * H + k] : 0.0f;
        s_w1i[i] = v ? w_ih1[row * H + k] : 0.0f;
        s_w1h[i] = v ? w_hh1[row * H + k] : 0.0f;
    }
    for (int i = tid; i < 40; i += BLK) {
        int c = i & 1, p = (i >> 1) & 1, a = i >> 2;
        int row = a + p * 20 + c * 10;
        s_b0p[i] = b_ih0[row] + b_hh0[row];
        s_b1p[i] = b_ih1[row] + b_hh1[row];
    }
    for (int i = tid; i < 10 * HP; i += BLK) {
        int r = i / HP, k = i - r * HP;
        s_wc[i] = (k < H) ? w_cls[r * H + k] : 0.0f;
    }
    if (tid < 10) s_bc[tid] = b_cls[tid];
    __syncthreads();

    const int r = tid >> 1;          // sample-in-CTA
    const int l = tid & 1;           // lane within pair
    const int A = l * 5;             // first owned unit
    const size_t sample = (size_t)blockIdx.x * SPB + r;

    // state: full h vectors (both lanes), private c for owned units
    float h0[HP], h1[HP], hn[HP], c0[5], c1[5], hown[5], h1own[5];
    #pragma unroll
    for (int i = 0; i < HP; i++) { h0[i] = 0.0f; h1[i] = 0.0f; hn[i] = 0.0f; }
    #pragma unroll
    for (int i = 0; i < 5; i++) { c0[i] = 0.0f; c1[i] = 0.0f; }

    const int s_init = tid / D;
    const int d_init = tid - s_init * D;
    const float* xblk = x + (size_t)blockIdx.x * SPB * (T * D);

    for (int t = 0; t < T; t++) {
        __syncthreads();
        {   // coalesced stage of x[64 samples][t][0..27] -> s_x (stride 30)
            const float* src = xblk + t * D;
            int e = tid, s = s_init, d = d_init;
            #pragma unroll
            for (int k = 0; k < SPB * D / BLK; k++) {   // 14
                s_x[e + 2 * s] = src[e + s * (T * D - D)];
                e += BLK;
                d += (BLK - 4 * D);   // +16
                s += 4;
                if (d >= D) { d -= D; s += 1; }
            }
        }
        __syncthreads();

        // x row -> duplicated f32x2 operands
        uint64_t xd[D];
        #pragma unroll
        for (int q = 0; q < D / 2; q++) {
            float2 v = *(const float2*)(s_x + r * SXS + 2 * q);
            xd[2 * q] = dup2(v.x);
            xd[2 * q + 1] = dup2(v.y);
        }

        // ---------- layer 0 ----------
        uint64_t acc[5][2];
        #pragma unroll
        for (int u = 0; u < 5; u++)
            #pragma unroll
            for (int p = 0; p < 2; p++)
                acc[u][p] = *(const uint64_t*)(s_b0p + ((A + u) * 2 + p) * 2);

        #pragma unroll
        for (int u = 0; u < 5; u++) {
            #pragma unroll
            for (int p = 0; p < 2; p++) {
                const ulonglong2* wp =
                    (const ulonglong2*)(s_wx + ((A + u) * 2 + p) * (D * 2));
                #pragma unroll
                for (int q = 0; q < D / 2; q++) {
                    ulonglong2 w = wp[q];
                    fma2(acc[u][p], w.x, xd[2 * q]);
                    fma2(acc[u][p], w.y, xd[2 * q + 1]);
                }
            }
        }
        {
            uint64_t hd[HP];
            #pragma unroll
            for (int k = 0; k < HP; k++) hd[k] = dup2(h0[k]);
            #pragma unroll
            for (int u = 0; u < 5; u++) {
                #pragma unroll
                for (int p = 0; p < 2; p++) {
                    const ulonglong2* wp =
                        (const ulonglong2*)(s_w0h + ((A + u) * 2 + p) * (HP * 2));
                    #pragma unroll
                    for (int q = 0; q < HP / 2; q++) {
                        ulonglong2 w = wp[q];
                        fma2(acc[u][p], w.x, hd[2 * q]);
                        fma2(acc[u][p], w.y, hd[2 * q + 1]);
                    }
                }
            }
        }
        #pragma unroll
        for (int u = 0; u < 5; u++) {
            float iv, fv, gv, ov;
            unp2(acc[u][0], iv, fv);
            unp2(acc[u][1], gv, ov);
            iv = sigm(iv); fv = sigm(fv); gv = tanh_(gv); ov = sigm(ov);
            float cn = fmaf(fv, c0[u], iv * gv);
            c0[u] = cn;
            hown[u] = ov * tanh_(cn);
        }
        // exchange -> full hn
        #pragma unroll
        for (int u = 0; u < 5; u++) {
            float oth = __shfl_xor_sync(0xffffffffu, hown[u], 1);
            hn[u]     = l ? oth : hown[u];
            hn[u + 5] = l ? hown[u] : oth;
        }

        // ---------- layer 1 ----------
        #pragma unroll
        for (int u = 0; u < 5; u++)
            #pragma unroll
            for (int p = 0; p < 2; p++)
                acc[u][p] = *(const uint64_t*)(s_b1p + ((A + u) * 2 + p) * 2);
        {
            uint64_t hd[HP];
            #pragma unroll
            for (int k = 0; k < HP; k++) hd[k] = dup2(hn[k]);
            #pragma unroll
            for (int u = 0; u < 5; u++) {
                #pragma unroll
                for (int p = 0; p < 2; p++) {
                    const ulonglong2* wp =
                        (const ulonglong2*)(s_w1i + ((A + u) * 2 + p) * (HP * 2));
                    #pragma unroll
                    for (int q = 0; q < HP / 2; q++) {
                        ulonglong2 w = wp[q];
                        fma2(acc[u][p], w.x, hd[2 * q]);
                        fma2(acc[u][p], w.y, hd[2 * q + 1]);
                    }
                }
            }
            #pragma unroll
            for (int k = 0; k < HP; k++) hd[k] = dup2(h1[k]);
            #pragma unroll
            for (int u = 0; u < 5; u++) {
                #pragma unroll
                for (int p = 0; p < 2; p++) {
                    const ulonglong2* wp =
                        (const ulonglong2*)(s_w1h + ((A + u) * 2 + p) * (HP * 2));
                    #pragma unroll
                    for (int q = 0; q < HP / 2; q++) {
                        ulonglong2 w = wp[q];
                        fma2(acc[u][p], w.x, hd[2 * q]);
                        fma2(acc[u][p], w.y, hd[2 * q + 1]);
                    }
                }
            }
        }
        #pragma unroll
        for (int u = 0; u < 5; u++) {
            float iv, fv, gv, ov;
            unp2(acc[u][0], iv, fv);
            unp2(acc[u][1], gv, ov);
            iv = sigm(iv); fv = sigm(fv); gv = tanh_(gv); ov = sigm(ov);
            float cn = fmaf(fv, c1[u], iv * gv);
            c1[u] = cn;
            h1own[u] = ov * tanh_(cn);
        }
        #pragma unroll
        for (int u = 0; u < 5; u++) {
            float oth = __shfl_xor_sync(0xffffffffu, h1own[u], 1);
            h1[u]     = l ? oth : h1own[u];
            h1[u + 5] = l ? h1own[u] : oth;
        }

        #pragma unroll
        for (int u = 0; u < H; u++) h0[u] = hn[u];
    }

    // ---------- classifier: lane writes its 5 output rows ----------
    #pragma unroll
    for (int j = 0; j < 5; j++) {
        const int row = A + j;
        float acc = s_bc[row];
        const float4* w = (const float4*)(s_wc + row * HP);
        #pragma unroll
        for (int q = 0; q < HP / 4; q++) {
            float4 a = w[q];
            acc += a.x * h1[4 * q];     acc += a.y * h1[4 * q + 1];
            acc += a.z * h1[4 * q + 2]; acc += a.w * h1[4 * q + 3];
        }
        out[sample * 10 + row] = acc;
    }
}
} // namespace

extern "C" void kernel_launch(void* const* d_in, const int* in_sizes, int n_in,
                              void* d_out, int out_size)
{
    (void)in_sizes; (void)n_in; (void)out_size;
    const float* x     = (const float*)d_in[0];
    const float* w_ih0 = (const float*)d_in[1];
    const float* w_hh0 = (const float*)d_in[2];
    const float* b_ih0 = (const float*)d_in[3];
    const float* b_hh0 = (const float*)d_in[4];
    const float* w_ih1 = (const float*)d_in[5];
    const float* w_hh1 = (const float*)d_in[6];
    const float* b_ih1 = (const float*)d_in[7];
    const float* b_hh1 = (const float*)d_in[8];
    const float* w_cls = (const float*)d_in[9];
    const float* b_cls = (const float*)d_in[10];

    lstm_all<<<BTOT / SPB, BLK>>>(x, w_ih0, w_hh0, b_ih0, b_hh0,
                                  w_ih1, w_hh1, b_ih1, b_hh1,
                                  w_cls, b_cls, (float*)d_out);
}